// round 11
// baseline (speedup 1.0000x reference)
#include <cuda_runtime.h>
#include <cuda_fp16.h>
#include <cstdint>

// ==================== problem constants ====================
constexpr int Dh  = 128;
constexpr int SQ  = 2048;
constexpr int SKV = 2048;
constexpr int NB  = 8;
constexpr int BM  = 128;        // q rows per CTA
constexpr int BN  = 64;         // keys per tile
constexpr int NT  = SKV / BN;   // 32
constexpr int NTHREADS = 256;

// V plane keeps the padded fp16 layout for ldmatrix.trans
constexpr int RSTRIDE = 272;

// smem layout
constexpr int SM_QA   = 0;          // Q digit-1 int8, 128 rows (16 groups x 1024B)
constexpr int SM_QB   = 16384;      // Q digit-2
constexpr int SM_STG  = 32768;
constexpr int OFF_KA  = 0;          // K digit-1 (8KB)
constexpr int OFF_KB  = 8192;       // K digit-2 (8KB)
constexpr int OFF_V   = 16384;      // V fp16 plane (64 x 272 = 17408)
constexpr int OFF_KS  = 33792;      // K row scales (64 floats)
constexpr int STG_SZ  = 34048;
constexpr int SMEM_TOTAL = SM_STG + 2 * STG_SZ;   // 100864

// ==================== device scratch ====================
// int8 digit planes in fragment-native tile-blocked layout:
// addr = (row/8)*1024 + ks*256 + ((row%8)*4 + p)*8 + h*4 + b
//   covering element k = ks*32 + (p + 4h)*4 + b
__device__ int8_t g_Qa[NB * SQ * Dh];
__device__ int8_t g_Qb[NB * SQ * Dh];
__device__ int8_t g_Ka[NB * SKV * Dh];
__device__ int8_t g_Kb[NB * SKV * Dh];
__device__ float  g_Qs[NB * SQ];
__device__ float  g_Ks[NB * SKV];
__device__ __half g_Vh[NB * SKV * Dh];

// ==================== helpers ====================
__device__ __forceinline__ uint32_t smem_u32(const void* p) {
    uint32_t a;
    asm("{ .reg .u64 t; cvta.to.shared.u64 t, %1; cvt.u32.u64 %0, t; }"
        : "=r"(a) : "l"(p));
    return a;
}

__device__ __forceinline__ uint32_t pack2h(float lo, float hi) {
    __half2 h = __floats2half2_rn(lo, hi);
    return *reinterpret_cast<uint32_t*>(&h);
}

// mma m16n8k16 fp16 -> fp32 accum (PV)
__device__ __forceinline__ void mma16816(float d[4], const uint32_t a[4], const uint32_t b[2]) {
    asm volatile(
        "mma.sync.aligned.m16n8k16.row.col.f32.f16.f16.f32 "
        "{%0,%1,%2,%3}, {%4,%5,%6,%7}, {%8,%9}, {%0,%1,%2,%3};"
        : "+f"(d[0]), "+f"(d[1]), "+f"(d[2]), "+f"(d[3])
        : "r"(a[0]), "r"(a[1]), "r"(a[2]), "r"(a[3]), "r"(b[0]), "r"(b[1]));
}

// mma m16n8k32 s8 -> s32 accum (QK)
__device__ __forceinline__ void imma(int d[4], const uint32_t a[4], const uint32_t b[2]) {
    asm volatile(
        "mma.sync.aligned.m16n8k32.row.col.s32.s8.s8.s32 "
        "{%0,%1,%2,%3}, {%4,%5,%6,%7}, {%8,%9}, {%0,%1,%2,%3};"
        : "+r"(d[0]), "+r"(d[1]), "+r"(d[2]), "+r"(d[3])
        : "r"(a[0]), "r"(a[1]), "r"(a[2]), "r"(a[3]), "r"(b[0]), "r"(b[1]));
}

__device__ __forceinline__ void ldsm_x4t(uint32_t r[4], uint32_t addr) {
    asm volatile("ldmatrix.sync.aligned.m8n8.x4.trans.shared.b16 {%0,%1,%2,%3}, [%4];"
        : "=r"(r[0]), "=r"(r[1]), "=r"(r[2]), "=r"(r[3]) : "r"(addr));
}

__device__ __forceinline__ void lds64(uint32_t& r0, uint32_t& r1, uint32_t addr) {
    asm volatile("ld.shared.v2.u32 {%0,%1}, [%2];" : "=r"(r0), "=r"(r1) : "r"(addr));
}

__device__ __forceinline__ void cpa16(uint32_t dst, const void* src) {
    asm volatile("cp.async.cg.shared.global [%0], [%1], 16;" :: "r"(dst), "l"(src));
}
#define CP_COMMIT() asm volatile("cp.async.commit_group;" ::: "memory")
#define CP_WAIT1()  asm volatile("cp.async.wait_group 1;" ::: "memory")

__device__ __forceinline__ void load_stage(uint32_t sb, int stg, int bbb, int jt, int tid) {
    uint32_t base = sb + SM_STG + stg * STG_SZ;
    size_t grp = (((size_t)bbb * SKV + (size_t)jt * BN) >> 3) * 1024;   // byte offset
    #pragma unroll
    for (int i = 0; i < 2; i++) {
        int c = tid + NTHREADS * i;          // 0..511
        cpa16(base + OFF_KA + c * 16, g_Ka + grp + c * 16);
        cpa16(base + OFF_KB + c * 16, g_Kb + grp + c * 16);
    }
    const __half* vs = g_Vh + ((size_t)bbb * SKV + (size_t)jt * BN) * Dh;
    #pragma unroll
    for (int i = 0; i < 4; i++) {
        int c = tid + NTHREADS * i;          // 0..1023
        int row = c >> 4, col = c & 15;
        cpa16(base + OFF_V + row * RSTRIDE + col * 16, vs + row * Dh + col * 8);
    }
    if (tid < 16)
        cpa16(base + OFF_KS + tid * 16, g_Ks + (size_t)bbb * SKV + jt * BN + tid * 4);
}

// ==================== prep: quantize Q/K to 2-digit int8 ====================
__global__ void __launch_bounds__(NTHREADS)
prep_quant(const float4* __restrict__ x1, const float4* __restrict__ x2)
{
    const int lane = threadIdx.x & 31;
    const int wid  = threadIdx.x >> 5;
    const int R    = blockIdx.x * 8 + wid;          // global row
    const float4* src = blockIdx.y ? x2 : x1;
    int8_t* da = blockIdx.y ? g_Ka : g_Qa;
    int8_t* db = blockIdx.y ? g_Kb : g_Qb;
    float*  ds = blockIdx.y ? g_Ks : g_Qs;

    float4 v = src[(size_t)R * 32 + lane];          // chunk = lane (k = 4*lane..+3)
    float m = fmaxf(fmaxf(fabsf(v.x), fabsf(v.y)), fmaxf(fabsf(v.z), fabsf(v.w)));
    #pragma unroll
    for (int o = 16; o; o >>= 1) m = fmaxf(m, __shfl_xor_sync(0xffffffffu, m, o));
    m = fmaxf(m, 1e-20f);
    float qs  = m * (1.0f / 127.0f);
    float inv = 127.0f / m;

    float f[4] = { v.x * inv, v.y * inv, v.z * inv, v.w * inv };
    uint32_t pa = 0, pb = 0;
    #pragma unroll
    for (int e = 0; e < 4; e++) {
        int a1 = __float2int_rn(f[e]);
        float r = f[e] - (float)a1;
        int a2 = __float2int_rn(r * 256.0f);
        a2 = min(a2, 127);
        pa |= (uint32_t)(a1 & 0xFF) << (8 * e);
        pb |= (uint32_t)(a2 & 0xFF) << (8 * e);
    }
    int ks = lane >> 3;
    int cl = lane & 7;
    int h  = cl >> 2;
    int p4 = cl & 3;
    size_t off = ((size_t)(R >> 3)) * 1024 + ks * 256 + ((R & 7) * 4 + p4) * 8 + h * 4;
    *reinterpret_cast<uint32_t*>(da + off) = pa;
    *reinterpret_cast<uint32_t*>(db + off) = pb;
    if (lane == 0) ds[R] = qs;
}

// ==================== prep: V fp32 -> fp16 row-major ====================
__global__ void __launch_bounds__(NTHREADS)
prep_v(const float4* __restrict__ x3)
{
    int i = blockIdx.x * NTHREADS + threadIdx.x;
    float4 v = x3[i];
    *reinterpret_cast<uint2*>(g_Vh + (size_t)i * 4) =
        make_uint2(pack2h(v.x, v.y), pack2h(v.z, v.w));
}

// ==================== main kernel ====================
__global__ void __launch_bounds__(NTHREADS, 1)
attn_main(const float* __restrict__ mask, float* __restrict__ out)
{
    extern __shared__ char smem[];
    const uint32_t sb = smem_u32(smem);
    const int tid  = threadIdx.x;
    const int w    = tid >> 5;      // warp: q rows 16w..16w+15
    const int lane = tid & 31;
    const int qc   = lane & 3;
    const int qr   = lane >> 2;
    const int bbt  = blockIdx.x >> 4;
    const int qt   = blockIdx.x & 15;

    // ---- prologue: Q int8 planes + stage0, stage1 ----
    {
        size_t qgrp = (((size_t)bbt * SQ + (size_t)qt * BM) >> 3) * 1024;
        #pragma unroll
        for (int i = 0; i < 4; i++) {
            int c = tid + NTHREADS * i;      // 0..1023
            cpa16(sb + SM_QA + c * 16, g_Qa + qgrp + c * 16);
            cpa16(sb + SM_QB + c * 16, g_Qb + qgrp + c * 16);
        }
        load_stage(sb, 0, bbt, 0, tid);
        CP_COMMIT();
        load_stage(sb, 1, bbt, 1, tid);
        CP_COMMIT();
    }

    float oacc[16][4] = {};
    float lac0 = 0.f, lac1 = 0.f;
    float m0r = -1e30f, m1r = -1e30f;

    const int row_g = qt * BM + 16 * w + qr;
    const float* mk0 = mask + ((size_t)bbt * SQ + row_g) * SKV;
    const float* mk1 = mk0 + (size_t)8 * SKV;

    const float qs0 = g_Qs[(size_t)bbt * SQ + qt * BM + 16 * w + qr];
    const float qs1 = g_Qs[(size_t)bbt * SQ + qt * BM + 16 * w + qr + 8];

    const uint32_t qaA = sb + SM_QA + (uint32_t)(2 * w) * 1024 + (uint32_t)lane * 8;
    const uint32_t qaB = qaA + (uint32_t)(SM_QB - SM_QA);

    constexpr float C8  = 1.0f / 256.0f;
    constexpr float C16 = 1.0f / 65536.0f;

    #pragma unroll 1
    for (int j = 0; j < NT; j++) {
        CP_WAIT1();
        __syncthreads();

        // ---- mask prefetch (latency hides under QK MMAs) ----
        float2 mreg[8][2];
        #pragma unroll
        for (int jj = 0; jj < 8; jj++) {
            mreg[jj][0] = *reinterpret_cast<const float2*>(mk0 + (size_t)j * BN + jj * 8 + 2 * qc);
            mreg[jj][1] = *reinterpret_cast<const float2*>(mk1 + (size_t)j * BN + jj * 8 + 2 * qc);
        }

        const uint32_t stg = sb + SM_STG + (uint32_t)(j & 1) * STG_SZ;
        const char* stgp = smem + SM_STG + (j & 1) * STG_SZ;

        // ---- QK: 2-digit int8, 4 integer passes, exact s32 accumulation ----
        float sacc[8][4];
        #pragma unroll
        for (int h4 = 0; h4 < 2; h4++) {
            int aa[4][4] = {}, xx[4][4] = {}, bb2[4][4] = {};
            #pragma unroll
            for (int ks = 0; ks < 4; ks++) {
                uint32_t a1[4], a2[4];
                lds64(a1[0], a1[2], qaA + ks * 256);
                lds64(a1[1], a1[3], qaA + 1024 + ks * 256);
                lds64(a2[0], a2[2], qaB + ks * 256);
                lds64(a2[1], a2[3], qaB + 1024 + ks * 256);
                uint32_t b1[4][2], b2[4][2];
                #pragma unroll
                for (int g = 0; g < 4; g++) {
                    uint32_t kb = stg + OFF_KA + (uint32_t)(h4 * 4 + g) * 1024 + ks * 256 + lane * 8;
                    lds64(b1[g][0], b1[g][1], kb);
                    lds64(b2[g][0], b2[g][1], kb + (OFF_KB - OFF_KA));
                }
                #pragma unroll
                for (int g = 0; g < 4; g++) imma(aa[g],  a1, b1[g]);
                #pragma unroll
                for (int g = 0; g < 4; g++) imma(xx[g],  a1, b2[g]);
                #pragma unroll
                for (int g = 0; g < 4; g++) imma(xx[g],  a2, b1[g]);
                #pragma unroll
                for (int g = 0; g < 4; g++) imma(bb2[g], a2, b2[g]);
            }
            #pragma unroll
            for (int g = 0; g < 4; g++) {
                const int jj = h4 * 4 + g;
                float2 kscv = *reinterpret_cast<const float2*>(
                    stgp + OFF_KS + (jj * 8 + 2 * qc) * 4);
                float s00 = qs0 * kscv.x, s01 = qs0 * kscv.y;
                float s10 = qs1 * kscv.x, s11 = qs1 * kscv.y;
                sacc[jj][0] = ((float)aa[g][0] + (float)xx[g][0] * C8 + (float)bb2[g][0] * C16) * s00;
                sacc[jj][1] = ((float)aa[g][1] + (float)xx[g][1] * C8 + (float)bb2[g][1] * C16) * s01;
                sacc[jj][2] = ((float)aa[g][2] + (float)xx[g][2] * C8 + (float)bb2[g][2] * C16) * s10;
                sacc[jj][3] = ((float)aa[g][3] + (float)xx[g][3] * C8 + (float)bb2[g][3] * C16) * s11;
            }
        }

        // ---- online softmax: p = exp(s - m_running) in (0,1] -> fp16-safe ----
        float tmax0 = -1e30f, tmax1 = -1e30f;
        #pragma unroll
        for (int jj = 0; jj < 8; jj++) {
            tmax0 = fmaxf(tmax0, fmaxf(sacc[jj][0], sacc[jj][1]));
            tmax1 = fmaxf(tmax1, fmaxf(sacc[jj][2], sacc[jj][3]));
        }
        tmax0 = fmaxf(tmax0, __shfl_xor_sync(0xffffffffu, tmax0, 1));
        tmax0 = fmaxf(tmax0, __shfl_xor_sync(0xffffffffu, tmax0, 2));
        tmax1 = fmaxf(tmax1, __shfl_xor_sync(0xffffffffu, tmax1, 1));
        tmax1 = fmaxf(tmax1, __shfl_xor_sync(0xffffffffu, tmax1, 2));
        float nm0 = fmaxf(m0r, tmax0);
        float nm1 = fmaxf(m1r, tmax1);
        float alpha0 = __expf(m0r - nm0);
        float alpha1 = __expf(m1r - nm1);
        m0r = nm0; m1r = nm1;
        if (!__all_sync(0xffffffffu, (alpha0 == 1.f) & (alpha1 == 1.f))) {
            lac0 *= alpha0;
            lac1 *= alpha1;
            #pragma unroll
            for (int j2 = 0; j2 < 16; j2++) {
                oacc[j2][0] *= alpha0; oacc[j2][1] *= alpha0;
                oacc[j2][2] *= alpha1; oacc[j2][3] *= alpha1;
            }
        }

        uint32_t ph[8][2];
        #pragma unroll
        for (int jj = 0; jj < 8; jj++) {
            float p0 = __expf(sacc[jj][0] - nm0);
            float p1 = __expf(sacc[jj][1] - nm0);
            float p2 = __expf(sacc[jj][2] - nm1);
            float p3 = __expf(sacc[jj][3] - nm1);
            lac0 += p0 + p1;
            lac1 += p2 + p3;
            p0 *= mreg[jj][0].x; p1 *= mreg[jj][0].y;
            p2 *= mreg[jj][1].x; p3 *= mreg[jj][1].y;
            ph[jj][0] = pack2h(p0, p1);
            ph[jj][1] = pack2h(p2, p3);
        }

        // ---- PV: single-pass fp16, pair-interleaved dv accumulators ----
        #pragma unroll
        for (int kkp = 0; kkp < 2; kkp++) {
            uint32_t aH0[4] = { ph[4*kkp  ][0], ph[4*kkp  ][1], ph[4*kkp+1][0], ph[4*kkp+1][1] };
            uint32_t aH1[4] = { ph[4*kkp+2][0], ph[4*kkp+2][1], ph[4*kkp+3][0], ph[4*kkp+3][1] };
            #pragma unroll
            for (int j2p = 0; j2p < 8; j2p++) {
                const int ja = 2 * j2p, jb = 2 * j2p + 1;
                uint32_t bHa[4], bHb[4];
                uint32_t va = stg + OFF_V + (32 * kkp + lane) * RSTRIDE + ja * 16;
                ldsm_x4t(bHa, va);
                ldsm_x4t(bHb, va + 16);
                mma16816(oacc[ja], aH0, &bHa[0]);  mma16816(oacc[jb], aH0, &bHb[0]);
                mma16816(oacc[ja], aH1, &bHa[2]);  mma16816(oacc[jb], aH1, &bHb[2]);
            }
        }

        __syncthreads();
        if (j + 2 < NT) load_stage(sb, j & 1, bbt, j + 2, tid);
        CP_COMMIT();
    }

    // ---- finalize: reduce l within quads (maxima already quad-uniform) ----
    lac0 += __shfl_xor_sync(0xffffffffu, lac0, 1);
    lac0 += __shfl_xor_sync(0xffffffffu, lac0, 2);
    lac1 += __shfl_xor_sync(0xffffffffu, lac1, 1);
    lac1 += __shfl_xor_sync(0xffffffffu, lac1, 2);
    float inv0 = 1.0f / lac0;
    float inv1 = 1.0f / lac1;

    float* o0 = out + ((size_t)bbt * SQ + row_g) * Dh;
    float* o1 = o0 + (size_t)8 * Dh;
    #pragma unroll
    for (int j2 = 0; j2 < 16; j2++) {
        *reinterpret_cast<float2*>(o0 + j2 * 8 + 2 * qc) =
            make_float2(oacc[j2][0] * inv0, oacc[j2][1] * inv0);
        *reinterpret_cast<float2*>(o1 + j2 * 8 + 2 * qc) =
            make_float2(oacc[j2][2] * inv1, oacc[j2][3] * inv1);
    }
}

// ==================== launch ====================
extern "C" void kernel_launch(void* const* d_in, const int* in_sizes, int n_in,
                              void* d_out, int out_size) {
    const float* x1   = (const float*)d_in[0];
    const float* x2   = (const float*)d_in[1];
    const float* x3   = (const float*)d_in[2];
    const float* mask = (const float*)d_in[3];
    float* out = (float*)d_out;

    dim3 qgrid(NB * SQ / 8, 2);                    // (2048, 2): warp per row
    prep_quant<<<qgrid, NTHREADS>>>((const float4*)x1, (const float4*)x2);
    prep_v<<<NB * SKV * Dh / 4 / NTHREADS, NTHREADS>>>((const float4*)x3);

    cudaFuncSetAttribute(attn_main,
                         cudaFuncAttributeMaxDynamicSharedMemorySize, SMEM_TOTAL);
    attn_main<<<128, NTHREADS, SMEM_TOTAL>>>(mask, out);
}

// round 12
// speedup vs baseline: 1.7268x; 1.7268x over previous
#include <cuda_runtime.h>
#include <cuda_fp16.h>
#include <cstdint>

// ==================== problem constants ====================
constexpr int Dh  = 128;
constexpr int SQ  = 2048;
constexpr int SKV = 2048;
constexpr int NB  = 8;
constexpr int BM  = 128;        // q rows per CTA
constexpr int BN  = 64;         // keys per tile
constexpr int NT  = SKV / BN;   // 32
constexpr int NTHREADS = 256;

// smem: padded 272B row stride (256B data + 16B) -> conflict-free ldmatrix
constexpr int RSTRIDE = 272;
constexpr int SM_QH  = 0;
constexpr int SM_QL  = SM_QH + BM * RSTRIDE;     // 34816
constexpr int SM_STG = SM_QL + BM * RSTRIDE;     // 69632
constexpr int PLANE  = BN * RSTRIDE;             // 17408
constexpr int STG_SZ = 3 * PLANE;                // 52224 (Khi, Klo, Vh)
constexpr int SMEM_TOTAL = SM_STG + 2 * STG_SZ;  // 174080

// ==================== device scratch (fp16 planes) ====================
__device__ __half g_Qh[NB * SQ * Dh];
__device__ __half g_Ql[NB * SQ * Dh];
__device__ __half g_Kh[NB * SKV * Dh];
__device__ __half g_Kl[NB * SKV * Dh];
__device__ __half g_Vh[NB * SKV * Dh];

// ==================== helpers ====================
__device__ __forceinline__ uint32_t smem_u32(const void* p) {
    uint32_t a;
    asm("{ .reg .u64 t; cvta.to.shared.u64 t, %1; cvt.u32.u64 %0, t; }"
        : "=r"(a) : "l"(p));
    return a;
}

__device__ __forceinline__ uint32_t pack2h(float lo, float hi) {
    __half2 h = __floats2half2_rn(lo, hi);
    return *reinterpret_cast<uint32_t*>(&h);
}

__device__ __forceinline__ void splitwh(float a, float b, uint32_t& hw, uint32_t& lw) {
    float ha = __half2float(__float2half_rn(a));
    float hb = __half2float(__float2half_rn(b));
    hw = pack2h(ha, hb);
    lw = pack2h(a - ha, b - hb);
}

// mma m16n8k16 fp16 -> fp32 accum
__device__ __forceinline__ void mma16816(float d[4], const uint32_t a[4], const uint32_t b[2]) {
    asm volatile(
        "mma.sync.aligned.m16n8k16.row.col.f32.f16.f16.f32 "
        "{%0,%1,%2,%3}, {%4,%5,%6,%7}, {%8,%9}, {%0,%1,%2,%3};"
        : "+f"(d[0]), "+f"(d[1]), "+f"(d[2]), "+f"(d[3])
        : "r"(a[0]), "r"(a[1]), "r"(a[2]), "r"(a[3]), "r"(b[0]), "r"(b[1]));
}

__device__ __forceinline__ void ldsm_x4(uint32_t r[4], uint32_t addr) {
    asm volatile("ldmatrix.sync.aligned.m8n8.x4.shared.b16 {%0,%1,%2,%3}, [%4];"
        : "=r"(r[0]), "=r"(r[1]), "=r"(r[2]), "=r"(r[3]) : "r"(addr));
}

__device__ __forceinline__ void ldsm_x4t(uint32_t r[4], uint32_t addr) {
    asm volatile("ldmatrix.sync.aligned.m8n8.x4.trans.shared.b16 {%0,%1,%2,%3}, [%4];"
        : "=r"(r[0]), "=r"(r[1]), "=r"(r[2]), "=r"(r[3]) : "r"(addr));
}

__device__ __forceinline__ void cpa16(uint32_t dst, const void* src) {
    asm volatile("cp.async.cg.shared.global [%0], [%1], 16;" :: "r"(dst), "l"(src));
}
#define CP_COMMIT() asm volatile("cp.async.commit_group;" ::: "memory")
#define CP_WAIT1()  asm volatile("cp.async.wait_group 1;" ::: "memory")

__device__ __forceinline__ void load_plane(uint32_t dst, const __half* src, int tid) {
    #pragma unroll
    for (int i = 0; i < 4; i++) {
        int c = tid + NTHREADS * i;          // 0..1023
        int row = c >> 4, col = c & 15;
        cpa16(dst + row * RSTRIDE + col * 16, src + row * Dh + col * 8);
    }
}

__device__ __forceinline__ void load_stage(uint32_t sb, int stg, int bb, int jt, int tid) {
    uint32_t base = sb + SM_STG + stg * STG_SZ;
    size_t g = ((size_t)bb * SKV + (size_t)jt * BN) * Dh;
    load_plane(base + 0 * PLANE, g_Kh + g, tid);
    load_plane(base + 1 * PLANE, g_Kl + g, tid);
    load_plane(base + 2 * PLANE, g_Vh + g, tid);
}

// load one QK b-fragment set: {b0H, b1H, b0L, b1L} for key-group pair jjp at k-slice sp
__device__ __forceinline__ void ld_bset(uint32_t b[16], uint32_t stg, uint32_t kaddr0,
                                        int jjp, int sp) {
    uint32_t ka = stg + kaddr0 + (uint32_t)((2 * jjp) * 8 * RSTRIDE + sp * 64);
    ldsm_x4(b + 0,  ka);
    ldsm_x4(b + 4,  ka + 8 * RSTRIDE);
    ldsm_x4(b + 8,  ka + PLANE);
    ldsm_x4(b + 12, ka + 8 * RSTRIDE + PLANE);
}

// ==================== prep kernel: fp32 -> fp16 hi/lo planes ====================
__global__ void __launch_bounds__(NTHREADS)
prep_kernel(const float4* __restrict__ x1, const float4* __restrict__ x2,
            const float4* __restrict__ x3)
{
    int t = blockIdx.y;
    const float4* src = (t == 0) ? x1 : (t == 1) ? x2 : x3;
    __half* dh = (t == 0) ? g_Qh : (t == 1) ? g_Kh : g_Vh;
    __half* dl = (t == 0) ? g_Ql : g_Kl;     // unused for t==2
    int i = blockIdx.x * NTHREADS + threadIdx.x;
    float4 v = src[i];
    uint32_t h0, l0, h1, l1;
    splitwh(v.x, v.y, h0, l0);
    splitwh(v.z, v.w, h1, l1);
    *reinterpret_cast<uint2*>(dh + (size_t)i * 4) = make_uint2(h0, h1);
    if (t < 2)
        *reinterpret_cast<uint2*>(dl + (size_t)i * 4) = make_uint2(l0, l1);
}

// ==================== main kernel ====================
__global__ void __launch_bounds__(NTHREADS, 1)
attn_main(const float* __restrict__ mask, float* __restrict__ out)
{
    extern __shared__ char smem[];
    const uint32_t sb = smem_u32(smem);
    const int tid  = threadIdx.x;
    const int w    = tid >> 5;      // warp: q rows 16w..16w+15
    const int lane = tid & 31;
    const int qc   = lane & 3;
    const int qr   = lane >> 2;
    const int bb   = blockIdx.x >> 4;
    const int qt   = blockIdx.x & 15;

    // ---- prologue: Q + stage0, stage1 ----
    {
        size_t qbase = ((size_t)bb * SQ + (size_t)qt * BM) * Dh;
        #pragma unroll
        for (int i = 0; i < 8; i++) {
            int c = tid + NTHREADS * i;
            int row = c >> 4, col = c & 15;
            cpa16(sb + SM_QH + row * RSTRIDE + col * 16, g_Qh + qbase + row * Dh + col * 8);
            cpa16(sb + SM_QL + row * RSTRIDE + col * 16, g_Ql + qbase + row * Dh + col * 8);
        }
        load_stage(sb, 0, bb, 0, tid);
        CP_COMMIT();
        load_stage(sb, 1, bb, 1, tid);
        CP_COMMIT();
    }

    float oacc[16][4] = {};
    float lac0 = 0.f, lac1 = 0.f;
    float m0r = -1e30f, m1r = -1e30f;   // running row maxima

    const int row_g = qt * BM + 16 * w + qr;
    const float* mk0 = mask + ((size_t)bb * SQ + row_g) * SKV;
    const float* mk1 = mk0 + (size_t)8 * SKV;

    const uint32_t qaddrH = sb + SM_QH + (16 * w + (lane & 15)) * RSTRIDE + (lane >> 4) * 16;
    const uint32_t qaddrL = qaddrH + (uint32_t)(SM_QL - SM_QH);
    const uint32_t kaddr0 = (uint32_t)((lane & 7) * RSTRIDE + ((lane >> 3) & 3) * 16);

    #pragma unroll 1
    for (int j = 0; j < NT; j++) {
        CP_WAIT1();
        __syncthreads();

        // ---- mask prefetch (latency hides under QK MMAs) ----
        float2 mreg[8][2];
        #pragma unroll
        for (int jj = 0; jj < 8; jj++) {
            mreg[jj][0] = *reinterpret_cast<const float2*>(mk0 + (size_t)j * BN + jj * 8 + 2 * qc);
            mreg[jj][1] = *reinterpret_cast<const float2*>(mk1 + (size_t)j * BN + jj * 8 + 2 * qc);
        }

        const uint32_t stg = sb + SM_STG + (uint32_t)(j & 1) * STG_SZ;

        // ---- QK: 3-pass fp16 emulation, b-fragments software-pipelined ----
        float sacc[8][4] = {};
        uint32_t bA[16], bB[16];
        ld_bset(bA, stg, kaddr0, 0, 0);
        #pragma unroll
        for (int sp = 0; sp < 4; sp++) {
            uint32_t aH0[4], aH1[4], aL0[4], aL1[4];
            ldsm_x4(aH0, qaddrH + sp * 64);
            ldsm_x4(aH1, qaddrH + sp * 64 + 32);
            ldsm_x4(aL0, qaddrL + sp * 64);
            ldsm_x4(aL1, qaddrL + sp * 64 + 32);
            #pragma unroll
            for (int jjp = 0; jjp < 4; jjp++) {
                uint32_t* cur = ((sp * 4 + jjp) & 1) ? bB : bA;
                uint32_t* nxt = ((sp * 4 + jjp) & 1) ? bA : bB;
                // prefetch next b-set: its ~35cyc latency hides under the 12 MMAs below
                if (!(sp == 3 && jjp == 3)) {
                    int njjp = (jjp + 1) & 3;
                    int nsp  = (jjp == 3) ? sp + 1 : sp;
                    ld_bset(nxt, stg, kaddr0, njjp, nsp);
                }
                float* s0 = sacc[2 * jjp];
                float* s1 = sacc[2 * jjp + 1];
                // hi*hi
                mma16816(s0, aH0, cur + 0);   mma16816(s1, aH0, cur + 4);
                mma16816(s0, aH1, cur + 2);   mma16816(s1, aH1, cur + 6);
                // cross terms (fp32 accum)
                mma16816(s0, aL0, cur + 0);   mma16816(s1, aL0, cur + 4);
                mma16816(s0, aH0, cur + 8);   mma16816(s1, aH0, cur + 12);
                mma16816(s0, aL1, cur + 2);   mma16816(s1, aL1, cur + 6);
                mma16816(s0, aH1, cur + 10);  mma16816(s1, aH1, cur + 14);
            }
        }

        // ---- prefetch first V fragments (independent of softmax below) ----
        uint32_t vA[8], vB[8];
        {
            uint32_t va0 = stg + 2 * PLANE + (uint32_t)lane * RSTRIDE;
            ldsm_x4t(vA,     va0);
            ldsm_x4t(vA + 4, va0 + 16);
        }

        // ---- online softmax: p = exp(s - m_running) in (0,1] -> fp16-safe ----
        float tmax0 = -1e30f, tmax1 = -1e30f;
        #pragma unroll
        for (int jj = 0; jj < 8; jj++) {
            tmax0 = fmaxf(tmax0, fmaxf(sacc[jj][0], sacc[jj][1]));
            tmax1 = fmaxf(tmax1, fmaxf(sacc[jj][2], sacc[jj][3]));
        }
        tmax0 = fmaxf(tmax0, __shfl_xor_sync(0xffffffffu, tmax0, 1));
        tmax0 = fmaxf(tmax0, __shfl_xor_sync(0xffffffffu, tmax0, 2));
        tmax1 = fmaxf(tmax1, __shfl_xor_sync(0xffffffffu, tmax1, 1));
        tmax1 = fmaxf(tmax1, __shfl_xor_sync(0xffffffffu, tmax1, 2));
        float nm0 = fmaxf(m0r, tmax0);
        float nm1 = fmaxf(m1r, tmax1);
        float alpha0 = __expf(m0r - nm0);
        float alpha1 = __expf(m1r - nm1);
        m0r = nm0; m1r = nm1;
        // skip O-rescale when every row's max is unchanged (common after warmup)
        if (!__all_sync(0xffffffffu, (alpha0 == 1.f) & (alpha1 == 1.f))) {
            lac0 *= alpha0;
            lac1 *= alpha1;
            #pragma unroll
            for (int j2 = 0; j2 < 16; j2++) {
                oacc[j2][0] *= alpha0; oacc[j2][1] *= alpha0;
                oacc[j2][2] *= alpha1; oacc[j2][3] *= alpha1;
            }
        }

        uint32_t ph[8][2];
        #pragma unroll
        for (int jj = 0; jj < 8; jj++) {
            float p0 = __expf(sacc[jj][0] - nm0);
            float p1 = __expf(sacc[jj][1] - nm0);
            float p2 = __expf(sacc[jj][2] - nm1);
            float p3 = __expf(sacc[jj][3] - nm1);
            lac0 += p0 + p1;
            lac1 += p2 + p3;
            p0 *= mreg[jj][0].x; p1 *= mreg[jj][0].y;
            p2 *= mreg[jj][1].x; p3 *= mreg[jj][1].y;
            ph[jj][0] = pack2h(p0, p1);
            ph[jj][1] = pack2h(p2, p3);
        }

        // ---- PV: single-pass fp16, V b-fragments double-buffered ----
        #pragma unroll
        for (int it = 0; it < 16; it++) {
            const int kkp = it >> 3;
            const int j2p = it & 7;
            uint32_t* cur = (it & 1) ? vB : vA;
            uint32_t* nxt = (it & 1) ? vA : vB;
            if (it < 15) {
                const int nit = it + 1;
                const int nk = nit >> 3, nj = nit & 7;
                uint32_t va = stg + 2 * PLANE + (uint32_t)((32 * nk + lane) * RSTRIDE + (2 * nj) * 16);
                ldsm_x4t(nxt,     va);
                ldsm_x4t(nxt + 4, va + 16);
            }
            const int ja = 2 * j2p, jb = 2 * j2p + 1;
            uint32_t aH0[4] = { ph[4*kkp  ][0], ph[4*kkp  ][1], ph[4*kkp+1][0], ph[4*kkp+1][1] };
            uint32_t aH1[4] = { ph[4*kkp+2][0], ph[4*kkp+2][1], ph[4*kkp+3][0], ph[4*kkp+3][1] };
            mma16816(oacc[ja], aH0, cur + 0);  mma16816(oacc[jb], aH0, cur + 4);
            mma16816(oacc[ja], aH1, cur + 2);  mma16816(oacc[jb], aH1, cur + 6);
        }

        __syncthreads();
        if (j + 2 < NT) load_stage(sb, j & 1, bb, j + 2, tid);
        CP_COMMIT();
    }

    // ---- finalize: reduce l within quads (maxima already quad-uniform) ----
    lac0 += __shfl_xor_sync(0xffffffffu, lac0, 1);
    lac0 += __shfl_xor_sync(0xffffffffu, lac0, 2);
    lac1 += __shfl_xor_sync(0xffffffffu, lac1, 1);
    lac1 += __shfl_xor_sync(0xffffffffu, lac1, 2);
    float inv0 = 1.0f / lac0;
    float inv1 = 1.0f / lac1;

    float* o0 = out + ((size_t)bb * SQ + row_g) * Dh;
    float* o1 = o0 + (size_t)8 * Dh;
    #pragma unroll
    for (int j2 = 0; j2 < 16; j2++) {
        *reinterpret_cast<float2*>(o0 + j2 * 8 + 2 * qc) =
            make_float2(oacc[j2][0] * inv0, oacc[j2][1] * inv0);
        *reinterpret_cast<float2*>(o1 + j2 * 8 + 2 * qc) =
            make_float2(oacc[j2][2] * inv1, oacc[j2][3] * inv1);
    }
}

// ==================== launch ====================
extern "C" void kernel_launch(void* const* d_in, const int* in_sizes, int n_in,
                              void* d_out, int out_size) {
    const float* x1   = (const float*)d_in[0];
    const float* x2   = (const float*)d_in[1];
    const float* x3   = (const float*)d_in[2];
    const float* mask = (const float*)d_in[3];
    float* out = (float*)d_out;

    dim3 pgrid(NB * SQ * Dh / 4 / NTHREADS, 3);
    prep_kernel<<<pgrid, NTHREADS>>>(
        (const float4*)x1, (const float4*)x2, (const float4*)x3);

    cudaFuncSetAttribute(attn_main,
                         cudaFuncAttributeMaxDynamicSharedMemorySize, SMEM_TOTAL);
    attn_main<<<128, NTHREADS, SMEM_TOTAL>>>(mask, out);
}

// round 13
// speedup vs baseline: 2.4679x; 1.4291x over previous
#include <cuda_runtime.h>
#include <cuda_fp16.h>
#include <cstdint>

// ==================== problem constants ====================
constexpr int Dh  = 128;
constexpr int SQ  = 2048;
constexpr int SKV = 2048;
constexpr int NB  = 8;
constexpr int BM  = 128;        // q rows per CTA
constexpr int BN  = 64;         // keys per tile
constexpr int NT  = SKV / BN;   // 32
constexpr int NTHREADS = 256;

// smem: padded 272B row stride (256B data + 16B) -> conflict-free ldmatrix
constexpr int RSTRIDE = 272;
constexpr int SM_QH  = 0;
constexpr int SM_QL  = SM_QH + BM * RSTRIDE;     // 34816
constexpr int SM_STG = SM_QL + BM * RSTRIDE;     // 69632
constexpr int PLANE  = BN * RSTRIDE;             // 17408
constexpr int STG_SZ = 3 * PLANE;                // 52224 (Khi, Klo, Vh)
constexpr int SMEM_TOTAL = SM_STG + 2 * STG_SZ;  // 174080

// ==================== device scratch (fp16 planes) ====================
__device__ __half g_Qh[NB * SQ * Dh];
__device__ __half g_Ql[NB * SQ * Dh];
__device__ __half g_Kh[NB * SKV * Dh];
__device__ __half g_Kl[NB * SKV * Dh];
__device__ __half g_Vh[NB * SKV * Dh];

// ==================== helpers ====================
__device__ __forceinline__ uint32_t smem_u32(const void* p) {
    uint32_t a;
    asm("{ .reg .u64 t; cvta.to.shared.u64 t, %1; cvt.u32.u64 %0, t; }"
        : "=r"(a) : "l"(p));
    return a;
}

__device__ __forceinline__ uint32_t pack2h(float lo, float hi) {
    __half2 h = __floats2half2_rn(lo, hi);
    return *reinterpret_cast<uint32_t*>(&h);
}

__device__ __forceinline__ void splitwh(float a, float b, uint32_t& hw, uint32_t& lw) {
    float ha = __half2float(__float2half_rn(a));
    float hb = __half2float(__float2half_rn(b));
    hw = pack2h(ha, hb);
    lw = pack2h(a - ha, b - hb);
}

// mma m16n8k16 fp16 -> fp32 accum
__device__ __forceinline__ void mma16816(float d[4], const uint32_t a[4], const uint32_t b[2]) {
    asm volatile(
        "mma.sync.aligned.m16n8k16.row.col.f32.f16.f16.f32 "
        "{%0,%1,%2,%3}, {%4,%5,%6,%7}, {%8,%9}, {%0,%1,%2,%3};"
        : "+f"(d[0]), "+f"(d[1]), "+f"(d[2]), "+f"(d[3])
        : "r"(a[0]), "r"(a[1]), "r"(a[2]), "r"(a[3]), "r"(b[0]), "r"(b[1]));
}

// mma m16n8k16 fp16 -> fp16 accum (cross terms: tiny values, range/rounding safe)
__device__ __forceinline__ void mma16816h(uint32_t c[2], const uint32_t a[4], const uint32_t b[2]) {
    asm volatile(
        "mma.sync.aligned.m16n8k16.row.col.f16.f16.f16.f16 "
        "{%0,%1}, {%2,%3,%4,%5}, {%6,%7}, {%0,%1};"
        : "+r"(c[0]), "+r"(c[1])
        : "r"(a[0]), "r"(a[1]), "r"(a[2]), "r"(a[3]), "r"(b[0]), "r"(b[1]));
}

__device__ __forceinline__ void ldsm_x4(uint32_t r[4], uint32_t addr) {
    asm volatile("ldmatrix.sync.aligned.m8n8.x4.shared.b16 {%0,%1,%2,%3}, [%4];"
        : "=r"(r[0]), "=r"(r[1]), "=r"(r[2]), "=r"(r[3]) : "r"(addr));
}

__device__ __forceinline__ void ldsm_x4t(uint32_t r[4], uint32_t addr) {
    asm volatile("ldmatrix.sync.aligned.m8n8.x4.trans.shared.b16 {%0,%1,%2,%3}, [%4];"
        : "=r"(r[0]), "=r"(r[1]), "=r"(r[2]), "=r"(r[3]) : "r"(addr));
}

__device__ __forceinline__ void cpa16(uint32_t dst, const void* src) {
    asm volatile("cp.async.cg.shared.global [%0], [%1], 16;" :: "r"(dst), "l"(src));
}
#define CP_COMMIT() asm volatile("cp.async.commit_group;" ::: "memory")
#define CP_WAIT1()  asm volatile("cp.async.wait_group 1;" ::: "memory")

__device__ __forceinline__ void load_plane(uint32_t dst, const __half* src, int tid) {
    #pragma unroll
    for (int i = 0; i < 4; i++) {
        int c = tid + NTHREADS * i;          // 0..1023
        int row = c >> 4, col = c & 15;
        cpa16(dst + row * RSTRIDE + col * 16, src + row * Dh + col * 8);
    }
}

__device__ __forceinline__ void load_stage(uint32_t sb, int stg, int bb, int jt, int tid) {
    uint32_t base = sb + SM_STG + stg * STG_SZ;
    size_t g = ((size_t)bb * SKV + (size_t)jt * BN) * Dh;
    load_plane(base + 0 * PLANE, g_Kh + g, tid);
    load_plane(base + 1 * PLANE, g_Kl + g, tid);
    load_plane(base + 2 * PLANE, g_Vh + g, tid);
}

// load the K-hi fragments (2x ldsm_x4 = 8 regs) for key-group pair jjp at k-slice sp
__device__ __forceinline__ void ld_bH(uint32_t b[8], uint32_t stg, uint32_t kaddr0,
                                      int jjp, int sp) {
    uint32_t ka = stg + kaddr0 + (uint32_t)((2 * jjp) * 8 * RSTRIDE + sp * 64);
    ldsm_x4(b + 0, ka);
    ldsm_x4(b + 4, ka + 8 * RSTRIDE);
}

// K-lo fragments (same addresses + PLANE)
__device__ __forceinline__ void ld_bL(uint32_t b[8], uint32_t stg, uint32_t kaddr0,
                                      int jjp, int sp) {
    uint32_t ka = stg + kaddr0 + (uint32_t)((2 * jjp) * 8 * RSTRIDE + sp * 64) + PLANE;
    ldsm_x4(b + 0, ka);
    ldsm_x4(b + 4, ka + 8 * RSTRIDE);
}

// ==================== prep kernel: fp32 -> fp16 hi/lo planes ====================
__global__ void __launch_bounds__(NTHREADS)
prep_kernel(const float4* __restrict__ x1, const float4* __restrict__ x2,
            const float4* __restrict__ x3)
{
    int t = blockIdx.y;
    const float4* src = (t == 0) ? x1 : (t == 1) ? x2 : x3;
    __half* dh = (t == 0) ? g_Qh : (t == 1) ? g_Kh : g_Vh;
    __half* dl = (t == 0) ? g_Ql : g_Kl;     // unused for t==2
    int i = blockIdx.x * NTHREADS + threadIdx.x;
    float4 v = src[i];
    uint32_t h0, l0, h1, l1;
    splitwh(v.x, v.y, h0, l0);
    splitwh(v.z, v.w, h1, l1);
    *reinterpret_cast<uint2*>(dh + (size_t)i * 4) = make_uint2(h0, h1);
    if (t < 2)
        *reinterpret_cast<uint2*>(dl + (size_t)i * 4) = make_uint2(l0, l1);
}

// ==================== main kernel ====================
__global__ void __launch_bounds__(NTHREADS, 1)
attn_main(const float* __restrict__ mask, float* __restrict__ out)
{
    extern __shared__ char smem[];
    const uint32_t sb = smem_u32(smem);
    const int tid  = threadIdx.x;
    const int w    = tid >> 5;      // warp: q rows 16w..16w+15
    const int lane = tid & 31;
    const int qc   = lane & 3;
    const int qr   = lane >> 2;
    const int bb   = blockIdx.x >> 4;
    const int qt   = blockIdx.x & 15;

    // ---- prologue: Q + stage0, stage1 ----
    {
        size_t qbase = ((size_t)bb * SQ + (size_t)qt * BM) * Dh;
        #pragma unroll
        for (int i = 0; i < 8; i++) {
            int c = tid + NTHREADS * i;
            int row = c >> 4, col = c & 15;
            cpa16(sb + SM_QH + row * RSTRIDE + col * 16, g_Qh + qbase + row * Dh + col * 8);
            cpa16(sb + SM_QL + row * RSTRIDE + col * 16, g_Ql + qbase + row * Dh + col * 8);
        }
        load_stage(sb, 0, bb, 0, tid);
        CP_COMMIT();
        load_stage(sb, 1, bb, 1, tid);
        CP_COMMIT();
    }

    float oacc[16][4] = {};
    float lac0 = 0.f, lac1 = 0.f;
    float m0r = -1e30f, m1r = -1e30f;   // running row maxima

    const int row_g = qt * BM + 16 * w + qr;
    const float* mk0 = mask + ((size_t)bb * SQ + row_g) * SKV;
    const float* mk1 = mk0 + (size_t)8 * SKV;

    const uint32_t qaddrH = sb + SM_QH + (16 * w + (lane & 15)) * RSTRIDE + (lane >> 4) * 16;
    const uint32_t qaddrL = qaddrH + (uint32_t)(SM_QL - SM_QH);
    const uint32_t kaddr0 = (uint32_t)((lane & 7) * RSTRIDE + ((lane >> 3) & 3) * 16);

    #pragma unroll 1
    for (int j = 0; j < NT; j++) {
        CP_WAIT1();
        __syncthreads();

        // ---- mask prefetch (latency hides under QK MMAs) ----
        float2 mreg[8][2];
        #pragma unroll
        for (int jj = 0; jj < 8; jj++) {
            mreg[jj][0] = *reinterpret_cast<const float2*>(mk0 + (size_t)j * BN + jj * 8 + 2 * qc);
            mreg[jj][1] = *reinterpret_cast<const float2*>(mk1 + (size_t)j * BN + jj * 8 + 2 * qc);
        }

        const uint32_t stg = sb + SM_STG + (uint32_t)(j & 1) * STG_SZ;

        // ---- QK: hh in fp32 accum, cross in fp16 accum; Kh pipelined, Kl JIT ----
        float sacc[8][4] = {};
        uint32_t cacc[8][2] = {};
        uint32_t bHa[8], bHb[8], bL[8];
        ld_bH(bHa, stg, kaddr0, 0, 0);
        #pragma unroll
        for (int sp = 0; sp < 4; sp++) {
            uint32_t aH0[4], aH1[4], aL0[4], aL1[4];
            ldsm_x4(aH0, qaddrH + sp * 64);
            ldsm_x4(aH1, qaddrH + sp * 64 + 32);
            ldsm_x4(aL0, qaddrL + sp * 64);
            ldsm_x4(aL1, qaddrL + sp * 64 + 32);
            #pragma unroll
            for (int jjp = 0; jjp < 4; jjp++) {
                uint32_t* cur = ((sp * 4 + jjp) & 1) ? bHb : bHa;
                uint32_t* nxt = ((sp * 4 + jjp) & 1) ? bHa : bHb;
                // JIT K-lo load: first consumer is MMA #5 -> ~60cyc of hh issue covers it
                ld_bL(bL, stg, kaddr0, jjp, sp);
                // prefetch next block's K-hi
                if (!(sp == 3 && jjp == 3)) {
                    int njjp = (jjp + 1) & 3;
                    int nsp  = (jjp == 3) ? sp + 1 : sp;
                    ld_bH(nxt, stg, kaddr0, njjp, nsp);
                }
                float*    s0 = sacc[2 * jjp];
                float*    s1 = sacc[2 * jjp + 1];
                uint32_t* c0 = cacc[2 * jjp];
                uint32_t* c1 = cacc[2 * jjp + 1];
                // hi*hi (fp32 accum)
                mma16816(s0, aH0, cur + 0);   mma16816(s1, aH0, cur + 4);
                mma16816(s0, aH1, cur + 2);   mma16816(s1, aH1, cur + 6);
                // cross terms (fp16 accum; values ~1e-3, range & rounding safe)
                mma16816h(c0, aL0, cur + 0);  mma16816h(c1, aL0, cur + 4);
                mma16816h(c0, aH0, bL + 0);   mma16816h(c1, aH0, bL + 4);
                mma16816h(c0, aL1, cur + 2);  mma16816h(c1, aL1, cur + 6);
                mma16816h(c0, aH1, bL + 2);   mma16816h(c1, aH1, bL + 6);
            }
        }
        // fold fp16 cross sums into fp32 scores
        #pragma unroll
        for (int jj = 0; jj < 8; jj++) {
            float2 ca = __half22float2(*reinterpret_cast<__half2*>(&cacc[jj][0]));
            float2 cb = __half22float2(*reinterpret_cast<__half2*>(&cacc[jj][1]));
            sacc[jj][0] += ca.x; sacc[jj][1] += ca.y;
            sacc[jj][2] += cb.x; sacc[jj][3] += cb.y;
        }

        // ---- online softmax: p = exp(s - m_running) in (0,1] -> fp16-safe ----
        float tmax0 = -1e30f, tmax1 = -1e30f;
        #pragma unroll
        for (int jj = 0; jj < 8; jj++) {
            tmax0 = fmaxf(tmax0, fmaxf(sacc[jj][0], sacc[jj][1]));
            tmax1 = fmaxf(tmax1, fmaxf(sacc[jj][2], sacc[jj][3]));
        }
        tmax0 = fmaxf(tmax0, __shfl_xor_sync(0xffffffffu, tmax0, 1));
        tmax0 = fmaxf(tmax0, __shfl_xor_sync(0xffffffffu, tmax0, 2));
        tmax1 = fmaxf(tmax1, __shfl_xor_sync(0xffffffffu, tmax1, 1));
        tmax1 = fmaxf(tmax1, __shfl_xor_sync(0xffffffffu, tmax1, 2));
        float nm0 = fmaxf(m0r, tmax0);
        float nm1 = fmaxf(m1r, tmax1);
        float alpha0 = __expf(m0r - nm0);
        float alpha1 = __expf(m1r - nm1);
        m0r = nm0; m1r = nm1;
        // skip O-rescale when every row's max is unchanged (common after warmup)
        if (!__all_sync(0xffffffffu, (alpha0 == 1.f) & (alpha1 == 1.f))) {
            lac0 *= alpha0;
            lac1 *= alpha1;
            #pragma unroll
            for (int j2 = 0; j2 < 16; j2++) {
                oacc[j2][0] *= alpha0; oacc[j2][1] *= alpha0;
                oacc[j2][2] *= alpha1; oacc[j2][3] *= alpha1;
            }
        }

        uint32_t ph[8][2];
        #pragma unroll
        for (int jj = 0; jj < 8; jj++) {
            float p0 = __expf(sacc[jj][0] - nm0);
            float p1 = __expf(sacc[jj][1] - nm0);
            float p2 = __expf(sacc[jj][2] - nm1);
            float p3 = __expf(sacc[jj][3] - nm1);
            lac0 += p0 + p1;
            lac1 += p2 + p3;
            p0 *= mreg[jj][0].x; p1 *= mreg[jj][0].y;
            p2 *= mreg[jj][1].x; p3 *= mreg[jj][1].y;
            ph[jj][0] = pack2h(p0, p1);
            ph[jj][1] = pack2h(p2, p3);
        }

        // ---- PV: single-pass fp16, pair-interleaved dv accumulators (R10 form) ----
        #pragma unroll
        for (int kkp = 0; kkp < 2; kkp++) {
            uint32_t aH0[4] = { ph[4*kkp  ][0], ph[4*kkp  ][1], ph[4*kkp+1][0], ph[4*kkp+1][1] };
            uint32_t aH1[4] = { ph[4*kkp+2][0], ph[4*kkp+2][1], ph[4*kkp+3][0], ph[4*kkp+3][1] };
            #pragma unroll
            for (int j2p = 0; j2p < 8; j2p++) {
                const int ja = 2 * j2p, jb = 2 * j2p + 1;
                uint32_t bHa2[4], bHb2[4];
                uint32_t va = stg + 2 * PLANE + (32 * kkp + lane) * RSTRIDE + ja * 16;
                ldsm_x4t(bHa2, va);
                ldsm_x4t(bHb2, va + 16);
                mma16816(oacc[ja], aH0, &bHa2[0]);  mma16816(oacc[jb], aH0, &bHb2[0]);
                mma16816(oacc[ja], aH1, &bHa2[2]);  mma16816(oacc[jb], aH1, &bHb2[2]);
            }
        }

        __syncthreads();
        if (j + 2 < NT) load_stage(sb, j & 1, bb, j + 2, tid);
        CP_COMMIT();
    }

    // ---- finalize: reduce l within quads (maxima already quad-uniform) ----
    lac0 += __shfl_xor_sync(0xffffffffu, lac0, 1);
    lac0 += __shfl_xor_sync(0xffffffffu, lac0, 2);
    lac1 += __shfl_xor_sync(0xffffffffu, lac1, 1);
    lac1 += __shfl_xor_sync(0xffffffffu, lac1, 2);
    float inv0 = 1.0f / lac0;
    float inv1 = 1.0f / lac1;

    float* o0 = out + ((size_t)bb * SQ + row_g) * Dh;
    float* o1 = o0 + (size_t)8 * Dh;
    #pragma unroll
    for (int j2 = 0; j2 < 16; j2++) {
        *reinterpret_cast<float2*>(o0 + j2 * 8 + 2 * qc) =
            make_float2(oacc[j2][0] * inv0, oacc[j2][1] * inv0);
        *reinterpret_cast<float2*>(o1 + j2 * 8 + 2 * qc) =
            make_float2(oacc[j2][2] * inv1, oacc[j2][3] * inv1);
    }
}

// ==================== launch ====================
extern "C" void kernel_launch(void* const* d_in, const int* in_sizes, int n_in,
                              void* d_out, int out_size) {
    const float* x1   = (const float*)d_in[0];
    const float* x2   = (const float*)d_in[1];
    const float* x3   = (const float*)d_in[2];
    const float* mask = (const float*)d_in[3];
    float* out = (float*)d_out;

    dim3 pgrid(NB * SQ * Dh / 4 / NTHREADS, 3);
    prep_kernel<<<pgrid, NTHREADS>>>(
        (const float4*)x1, (const float4*)x2, (const float4*)x3);

    cudaFuncSetAttribute(attn_main,
                         cudaFuncAttributeMaxDynamicSharedMemorySize, SMEM_TOTAL);
    attn_main<<<128, NTHREADS, SMEM_TOTAL>>>(mask, out);
}